// round 1
// baseline (speedup 1.0000x reference)
#include <cuda_runtime.h>
#include <math.h>

// Problem constants
#define L_   6
#define B_   2
#define T_   1024
#define D_   1024
#define H_   16
#define DH_  64
#define FF_  4096
#define V_   32000
#define KNB_ 4
#define DT_  0.1f

// ---------------------------------------------------------------------------
// Scratch (static device globals — no runtime allocation)
// ---------------------------------------------------------------------------
__device__ float g_x[B_ * T_ * D_];          // residual stream      (8 MB)
__device__ float g_h[B_ * T_ * D_];          // layernorm output     (8 MB)
__device__ float g_qkv[B_ * T_ * 3 * D_];    // qkv projections      (25 MB)
__device__ float g_scores[(size_t)B_ * H_ * T_ * T_]; // attn scores (134 MB)
__device__ float g_attn[B_ * T_ * D_];       // attention output     (8 MB)
__device__ float g_ff[B_ * T_ * FF_];        // MLP hidden           (32 MB)

// ---------------------------------------------------------------------------
// Embedding: x[b,t,:] = embed[tok[b,t],:] + pos[t,:]
// ---------------------------------------------------------------------------
__global__ void embed_kernel(const int* __restrict__ tokens,
                             const float* __restrict__ embed,
                             const float* __restrict__ pos) {
    int row = blockIdx.x;            // b*T + t
    int t = row & (T_ - 1);
    int tok = tokens[row];
    const float4* e = (const float4*)(embed + (size_t)tok * D_);
    const float4* p = (const float4*)(pos + (size_t)t * D_);
    float4* o = (float4*)(g_x + (size_t)row * D_);
    int c = threadIdx.x;             // 256 threads * 4 floats = 1024
    float4 ev = e[c], pv = p[c];
    ev.x += pv.x; ev.y += pv.y; ev.z += pv.z; ev.w += pv.w;
    o[c] = ev;
}

// ---------------------------------------------------------------------------
// Kuramoto phase update -> writes directly to output tail.
// Note: the attention bias 0.1*cos(phase) is constant along the softmax axis
// and therefore cancels — attention does not depend on phases.
// ---------------------------------------------------------------------------
__global__ void kuramoto_kernel(const float* __restrict__ phase,
                                const float* __restrict__ freq,
                                const float* __restrict__ coupling,
                                const float* __restrict__ nbr_w,
                                const int* __restrict__ nbr_idx,
                                float* __restrict__ out_tail) {
    int i = threadIdx.x;
    if (i < L_ * H_) {
        int l = i / H_;
        float ph = phase[i];
        float sync = 0.0f;
        #pragma unroll
        for (int k = 0; k < KNB_; k++) {
            int id = nbr_idx[i * KNB_ + k];
            sync += nbr_w[i * KNB_ + k] * sinf(phase[l * H_ + id] - ph);
        }
        out_tail[i] = ph + DT_ * (freq[i] + coupling[l] * sync);
    }
}

// ---------------------------------------------------------------------------
// LayerNorm: one block per row of D=1024, 256 threads, float4 per thread.
// ---------------------------------------------------------------------------
__global__ void ln_kernel(const float* __restrict__ x,
                          const float* __restrict__ g,
                          const float* __restrict__ b,
                          float* __restrict__ out) {
    int row = blockIdx.x;
    int c = threadIdx.x;             // float4 index 0..255
    float4 v = ((const float4*)(x + (size_t)row * D_))[c];
    float s  = v.x + v.y + v.z + v.w;
    float s2 = v.x * v.x + v.y * v.y + v.z * v.z + v.w * v.w;
    #pragma unroll
    for (int o = 16; o; o >>= 1) {
        s  += __shfl_down_sync(0xFFFFFFFFu, s, o);
        s2 += __shfl_down_sync(0xFFFFFFFFu, s2, o);
    }
    __shared__ float ss[8], ss2[8];
    __shared__ float mu_s, rstd_s;
    if ((c & 31) == 0) { ss[c >> 5] = s; ss2[c >> 5] = s2; }
    __syncthreads();
    if (c == 0) {
        float S = 0.f, S2 = 0.f;
        #pragma unroll
        for (int i = 0; i < 8; i++) { S += ss[i]; S2 += ss2[i]; }
        float mu = S * (1.0f / D_);
        float var = S2 * (1.0f / D_) - mu * mu;
        mu_s = mu;
        rstd_s = rsqrtf(var + 1e-5f);
    }
    __syncthreads();
    float mu = mu_s, rstd = rstd_s;
    float4 gv = ((const float4*)g)[c];
    float4 bv = ((const float4*)b)[c];
    float4 o4;
    o4.x = (v.x - mu) * rstd * gv.x + bv.x;
    o4.y = (v.y - mu) * rstd * gv.y + bv.y;
    o4.z = (v.z - mu) * rstd * gv.z + bv.z;
    o4.w = (v.w - mu) * rstd * gv.w + bv.w;
    ((float4*)(out + (size_t)row * D_))[c] = o4;
}

// ---------------------------------------------------------------------------
// NT-GEMM: C[M,N] (+)= A[M,K] * B[N,K]^T + bias[N]
// 128x128 block tile, BK=16, 256 threads, 8x8 per thread.
// All M,N multiples of 128; K multiple of 16 (guaranteed by problem shapes).
// ---------------------------------------------------------------------------
#define GBM 128
#define GBN 128
#define GBK 16
__global__ __launch_bounds__(256, 2)
void gemm_nt_kernel(const float* __restrict__ A, const float* __restrict__ Bw,
                    const float* __restrict__ bias, float* __restrict__ C,
                    int M, int N, int Kd, int accumulate) {
    __shared__ float As[GBK][GBM];
    __shared__ float Bs[GBK][GBN];
    int tid = threadIdx.x;
    int tx = tid & 15, ty = tid >> 4;
    const float* Ab = A + (size_t)blockIdx.y * GBM * Kd;
    const float* Bb = Bw + (size_t)blockIdx.x * GBN * Kd;
    float acc[8][8] = {};
    for (int k0 = 0; k0 < Kd; k0 += GBK) {
        #pragma unroll
        for (int i = 0; i < 2; i++) {
            int idx = tid + i * 256;         // 0..511
            int row = idx >> 2;              // 0..127
            int c4  = (idx & 3) * 4;
            float4 va = *(const float4*)(Ab + (size_t)row * Kd + k0 + c4);
            As[c4 + 0][row] = va.x; As[c4 + 1][row] = va.y;
            As[c4 + 2][row] = va.z; As[c4 + 3][row] = va.w;
            float4 vb = *(const float4*)(Bb + (size_t)row * Kd + k0 + c4);
            Bs[c4 + 0][row] = vb.x; Bs[c4 + 1][row] = vb.y;
            Bs[c4 + 2][row] = vb.z; Bs[c4 + 3][row] = vb.w;
        }
        __syncthreads();
        #pragma unroll
        for (int kk = 0; kk < GBK; kk++) {
            float a[8], b[8];
            #pragma unroll
            for (int i = 0; i < 8; i++) a[i] = As[kk][ty * 8 + i];
            #pragma unroll
            for (int j = 0; j < 8; j++) b[j] = Bs[kk][tx * 8 + j];
            #pragma unroll
            for (int i = 0; i < 8; i++)
                #pragma unroll
                for (int j = 0; j < 8; j++)
                    acc[i][j] += a[i] * b[j];
        }
        __syncthreads();
    }
    #pragma unroll
    for (int i = 0; i < 8; i++) {
        size_t row = (size_t)blockIdx.y * GBM + ty * 8 + i;
        #pragma unroll
        for (int j = 0; j < 8; j += 4) {
            size_t col = (size_t)blockIdx.x * GBN + tx * 8 + j;
            float4 r;
            r.x = acc[i][j + 0] + bias[col + 0];
            r.y = acc[i][j + 1] + bias[col + 1];
            r.z = acc[i][j + 2] + bias[col + 2];
            r.w = acc[i][j + 3] + bias[col + 3];
            float4* cp = (float4*)(C + row * N + col);
            if (accumulate) {
                float4 old = *cp;
                r.x += old.x; r.y += old.y; r.z += old.z; r.w += old.w;
            }
            *cp = r;
        }
    }
}

// ---------------------------------------------------------------------------
// Attention scores: S[bh,q,k] = scale * sum_d Q[q,d]*K[k,d]
// Q/K read strided out of g_qkv ([B,T,3,H,DH] -> row stride 3*D).
// 64x64 tile per block, DH=64 in one shot.
// ---------------------------------------------------------------------------
__global__ __launch_bounds__(256)
void scores_kernel(float scale) {
    int bh = blockIdx.z;
    int b = bh >> 4, h = bh & 15;
    const float* qb = g_qkv + (size_t)b * T_ * 3 * D_ + h * DH_;
    const float* kb = qb + D_;       // K is the second third
    __shared__ float Qs[64][65];
    __shared__ float Ks[64][65];
    int q0 = blockIdx.y * 64, k0 = blockIdx.x * 64;
    int tid = threadIdx.x;
    #pragma unroll
    for (int it = 0; it < 4; it++) {
        int i = tid + it * 256;          // 0..1023
        int r = i >> 4, c4 = (i & 15) * 4;
        float4 qv = *(const float4*)(qb + (size_t)(q0 + r) * 3 * D_ + c4);
        Qs[r][c4] = qv.x; Qs[r][c4 + 1] = qv.y; Qs[r][c4 + 2] = qv.z; Qs[r][c4 + 3] = qv.w;
        float4 kv = *(const float4*)(kb + (size_t)(k0 + r) * 3 * D_ + c4);
        Ks[r][c4] = kv.x; Ks[r][c4 + 1] = kv.y; Ks[r][c4 + 2] = kv.z; Ks[r][c4 + 3] = kv.w;
    }
    __syncthreads();
    int tx = tid & 15, ty = tid >> 4;
    float acc[4][4] = {};
    #pragma unroll 8
    for (int d = 0; d < DH_; d++) {
        float a[4], bb[4];
        #pragma unroll
        for (int i = 0; i < 4; i++) a[i] = Qs[ty * 4 + i][d];
        #pragma unroll
        for (int j = 0; j < 4; j++) bb[j] = Ks[tx * 4 + j][d];
        #pragma unroll
        for (int i = 0; i < 4; i++)
            #pragma unroll
            for (int j = 0; j < 4; j++)
                acc[i][j] += a[i] * bb[j];
    }
    float* srow = g_scores + (size_t)bh * T_ * T_;
    #pragma unroll
    for (int i = 0; i < 4; i++) {
        float4 r;
        r.x = acc[i][0] * scale; r.y = acc[i][1] * scale;
        r.z = acc[i][2] * scale; r.w = acc[i][3] * scale;
        *(float4*)(srow + (size_t)(q0 + ty * 4 + i) * T_ + k0 + tx * 4) = r;
    }
}

// ---------------------------------------------------------------------------
// Row softmax over T=1024 (bias cancels; scale pre-applied).
// ---------------------------------------------------------------------------
__global__ void softmax_kernel() {
    size_t row = blockIdx.x;
    int c = threadIdx.x;
    float4* rp = (float4*)(g_scores + row * T_);
    float4 v = rp[c];
    float m = fmaxf(fmaxf(v.x, v.y), fmaxf(v.z, v.w));
    #pragma unroll
    for (int o = 16; o; o >>= 1) m = fmaxf(m, __shfl_down_sync(0xFFFFFFFFu, m, o));
    __shared__ float sm[8];
    __shared__ float bm, bs;
    if ((c & 31) == 0) sm[c >> 5] = m;
    __syncthreads();
    if (c == 0) {
        float mm = sm[0];
        #pragma unroll
        for (int i = 1; i < 8; i++) mm = fmaxf(mm, sm[i]);
        bm = mm;
    }
    __syncthreads();
    float mm = bm;
    v.x = expf(v.x - mm); v.y = expf(v.y - mm);
    v.z = expf(v.z - mm); v.w = expf(v.w - mm);
    float s = v.x + v.y + v.z + v.w;
    #pragma unroll
    for (int o = 16; o; o >>= 1) s += __shfl_down_sync(0xFFFFFFFFu, s, o);
    if ((c & 31) == 0) sm[c >> 5] = s;
    __syncthreads();
    if (c == 0) {
        float S = 0.f;
        #pragma unroll
        for (int i = 0; i < 8; i++) S += sm[i];
        bs = 1.0f / S;
    }
    __syncthreads();
    float inv = bs;
    v.x *= inv; v.y *= inv; v.z *= inv; v.w *= inv;
    rp[c] = v;
}

// ---------------------------------------------------------------------------
// AV: O[bh,q,:] = sum_k S[bh,q,k] * V[bh,k,:]  -> g_attn [B,T,D] layout
// ---------------------------------------------------------------------------
__global__ __launch_bounds__(256)
void av_kernel() {
    int bh = blockIdx.y;
    int b = bh >> 4, h = bh & 15;
    int q0 = blockIdx.x * 64;
    const float* vb = g_qkv + (size_t)b * T_ * 3 * D_ + 2 * D_ + h * DH_;
    const float* srow = g_scores + (size_t)bh * T_ * T_;
    __shared__ float Ss[64][65];
    __shared__ float Vs[64][65];
    int tid = threadIdx.x;
    int tx = tid & 15, ty = tid >> 4;
    float acc[4][4] = {};
    for (int kk0 = 0; kk0 < T_; kk0 += 64) {
        #pragma unroll
        for (int it = 0; it < 4; it++) {
            int i = tid + it * 256;
            int r = i >> 4, c4 = (i & 15) * 4;
            float4 sv = *(const float4*)(srow + (size_t)(q0 + r) * T_ + kk0 + c4);
            Ss[r][c4] = sv.x; Ss[r][c4 + 1] = sv.y; Ss[r][c4 + 2] = sv.z; Ss[r][c4 + 3] = sv.w;
            float4 vv = *(const float4*)(vb + (size_t)(kk0 + r) * 3 * D_ + c4);
            Vs[r][c4] = vv.x; Vs[r][c4 + 1] = vv.y; Vs[r][c4 + 2] = vv.z; Vs[r][c4 + 3] = vv.w;
        }
        __syncthreads();
        #pragma unroll 8
        for (int k = 0; k < 64; k++) {
            float a[4], bb[4];
            #pragma unroll
            for (int i = 0; i < 4; i++) a[i] = Ss[ty * 4 + i][k];
            #pragma unroll
            for (int j = 0; j < 4; j++) bb[j] = Vs[k][tx * 4 + j];
            #pragma unroll
            for (int i = 0; i < 4; i++)
                #pragma unroll
                for (int j = 0; j < 4; j++)
                    acc[i][j] += a[i] * bb[j];
        }
        __syncthreads();
    }
    #pragma unroll
    for (int i = 0; i < 4; i++) {
        float4 r;
        r.x = acc[i][0]; r.y = acc[i][1]; r.z = acc[i][2]; r.w = acc[i][3];
        *(float4*)(g_attn + (size_t)(b * T_ + q0 + ty * 4 + i) * D_ + h * DH_ + tx * 4) = r;
    }
}

// ---------------------------------------------------------------------------
// GELU (tanh approximation, matching jax.nn.gelu approximate=True)
// ---------------------------------------------------------------------------
__global__ void gelu_kernel(float* __restrict__ x) {
    size_t i = ((size_t)blockIdx.x * 256 + threadIdx.x) * 4;
    float4 v = *(float4*)(x + i);
    #pragma unroll
    for (int k = 0; k < 4; k++) {
        float t = ((float*)&v)[k];
        float u = 0.7978845608028654f * (t + 0.044715f * t * t * t);
        ((float*)&v)[k] = 0.5f * t * (1.0f + tanhf(u));
    }
    *(float4*)(x + i) = v;
}

// ---------------------------------------------------------------------------
// Host launcher
// ---------------------------------------------------------------------------
extern "C" void kernel_launch(void* const* d_in, const int* in_sizes, int n_in,
                              void* d_out, int out_size) {
    const int*   tokens   = (const int*)  d_in[0];
    const float* embed    = (const float*)d_in[1];
    const float* pos      = (const float*)d_in[2];
    const float* qkv_w    = (const float*)d_in[3];
    const float* qkv_b    = (const float*)d_in[4];
    const float* out_w    = (const float*)d_in[5];
    const float* out_b    = (const float*)d_in[6];
    const float* fc1_w    = (const float*)d_in[7];
    const float* fc1_b    = (const float*)d_in[8];
    const float* fc2_w    = (const float*)d_in[9];
    const float* fc2_b    = (const float*)d_in[10];
    const float* ln1_g    = (const float*)d_in[11];
    const float* ln1_b    = (const float*)d_in[12];
    const float* ln2_g    = (const float*)d_in[13];
    const float* ln2_b    = (const float*)d_in[14];
    const float* lnf_g    = (const float*)d_in[15];
    const float* lnf_b    = (const float*)d_in[16];
    const float* head_w   = (const float*)d_in[17];
    const float* head_b   = (const float*)d_in[18];
    const float* phase    = (const float*)d_in[19];
    const float* freq     = (const float*)d_in[20];
    const float* coupling = (const float*)d_in[21];
    const float* nbr_w    = (const float*)d_in[22];
    const int*   nbr_idx  = (const int*)  d_in[23];
    float* out = (float*)d_out;

    float *px, *ph, *pqkv, *pattn, *pff;
    cudaGetSymbolAddress((void**)&px, g_x);
    cudaGetSymbolAddress((void**)&ph, g_h);
    cudaGetSymbolAddress((void**)&pqkv, g_qkv);
    cudaGetSymbolAddress((void**)&pattn, g_attn);
    cudaGetSymbolAddress((void**)&pff, g_ff);

    const int M = B_ * T_;   // 2048
    const float scale = 1.0f / 8.0f;  // 1/sqrt(64)

    // phases -> output tail (independent of everything else)
    kuramoto_kernel<<<1, 128>>>(phase, freq, coupling, nbr_w, nbr_idx,
                                out + (size_t)B_ * T_ * V_);

    embed_kernel<<<M, 256>>>(tokens, embed, pos);

    for (int l = 0; l < L_; l++) {
        ln_kernel<<<M, 256>>>(px, ln1_g + l * D_, ln1_b + l * D_, ph);
        gemm_nt_kernel<<<dim3(3 * D_ / GBN, M / GBM), 256>>>(
            ph, qkv_w + (size_t)l * 3 * D_ * D_, qkv_b + l * 3 * D_, pqkv,
            M, 3 * D_, D_, 0);
        scores_kernel<<<dim3(T_ / 64, T_ / 64, B_ * H_), 256>>>(scale);
        softmax_kernel<<<B_ * H_ * T_, 256>>>();
        av_kernel<<<dim3(T_ / 64, B_ * H_), 256>>>();
        gemm_nt_kernel<<<dim3(D_ / GBN, M / GBM), 256>>>(
            pattn, out_w + (size_t)l * D_ * D_, out_b + l * D_, px,
            M, D_, D_, 1);
        ln_kernel<<<M, 256>>>(px, ln2_g + l * D_, ln2_b + l * D_, ph);
        gemm_nt_kernel<<<dim3(FF_ / GBN, M / GBM), 256>>>(
            ph, fc1_w + (size_t)l * FF_ * D_, fc1_b + l * FF_, pff,
            M, FF_, D_, 0);
        gelu_kernel<<<(M * FF_) / 1024, 256>>>(pff);
        gemm_nt_kernel<<<dim3(D_ / GBN, M / GBM), 256>>>(
            pff, fc2_w + (size_t)l * D_ * FF_, fc2_b + l * D_, px,
            M, D_, FF_, 1);
    }

    ln_kernel<<<M, 256>>>(px, lnf_g, lnf_b, ph);
    gemm_nt_kernel<<<dim3(V_ / GBN, M / GBM), 256>>>(
        ph, head_w, head_b, out, M, V_, D_, 0);
}

// round 3
// speedup vs baseline: 1.9494x; 1.9494x over previous
#include <cuda_runtime.h>
#include <cuda_bf16.h>
#include <math.h>
#include <stdint.h>

// Problem constants
#define L_   6
#define B_   2
#define T_   1024
#define D_   1024
#define H_   16
#define DH_  64
#define FF_  4096
#define V_   32000
#define KNB_ 4
#define DT_  0.1f

// ---------------------------------------------------------------------------
// Scratch (static device globals)
// ---------------------------------------------------------------------------
__device__ float g_x[B_ * T_ * D_];
__device__ float g_h[B_ * T_ * D_];
__device__ float g_qkv[B_ * T_ * 3 * D_];
__device__ float g_scores[(size_t)B_ * H_ * T_ * T_];
__device__ float g_attn[B_ * T_ * D_];
__device__ float g_ff[B_ * T_ * FF_];

#define W_QKV_OFF  ((size_t)0)
#define W_QKV_N    ((size_t)L_ * 3 * D_ * D_)
#define W_OUT_OFF  (W_QKV_OFF + W_QKV_N)
#define W_OUT_N    ((size_t)L_ * D_ * D_)
#define W_FC1_OFF  (W_OUT_OFF + W_OUT_N)
#define W_FC1_N    ((size_t)L_ * FF_ * D_)
#define W_FC2_OFF  (W_FC1_OFF + W_FC1_N)
#define W_FC2_N    ((size_t)L_ * D_ * FF_)
#define W_HEAD_OFF (W_FC2_OFF + W_FC2_N)
#define W_HEAD_N   ((size_t)V_ * D_)
#define W_TOTAL    (W_HEAD_OFF + W_HEAD_N)

__device__ __nv_bfloat16 g_w_hi[W_TOTAL];
__device__ __nv_bfloat16 g_w_lo[W_TOTAL];
__device__ __nv_bfloat16 g_act_hi[B_ * T_ * FF_];
__device__ __nv_bfloat16 g_act_lo[B_ * T_ * FF_];

// ---------------------------------------------------------------------------
// helpers
// ---------------------------------------------------------------------------
__device__ __forceinline__ uint32_t smem_u32(const void* p) {
    uint32_t a;
    asm("{ .reg .u64 t; cvta.to.shared.u64 t, %1; cvt.u32.u64 %0, t; }" : "=r"(a) : "l"(p));
    return a;
}
__device__ __forceinline__ void ldmatrix_x4(uint32_t* r, uint32_t addr) {
    asm volatile("ldmatrix.sync.aligned.m8n8.x4.shared.b16 {%0,%1,%2,%3},[%4];"
                 : "=r"(r[0]), "=r"(r[1]), "=r"(r[2]), "=r"(r[3]) : "r"(addr));
}
__device__ __forceinline__ void ldmatrix_x2(uint32_t* r, uint32_t addr) {
    asm volatile("ldmatrix.sync.aligned.m8n8.x2.shared.b16 {%0,%1},[%2];"
                 : "=r"(r[0]), "=r"(r[1]) : "r"(addr));
}
__device__ __forceinline__ void mma_bf16(float* c, const uint32_t* a, const uint32_t* b) {
    asm volatile(
        "mma.sync.aligned.m16n8k16.row.col.f32.bf16.bf16.f32 "
        "{%0,%1,%2,%3},{%4,%5,%6,%7},{%8,%9},{%0,%1,%2,%3};"
        : "+f"(c[0]), "+f"(c[1]), "+f"(c[2]), "+f"(c[3])
        : "r"(a[0]), "r"(a[1]), "r"(a[2]), "r"(a[3]), "r"(b[0]), "r"(b[1]));
}
#define CP_ASYNC(dst, src) \
    asm volatile("cp.async.cg.shared.global [%0],[%1],16;" :: "r"(dst), "l"(src))
#define CP_COMMIT() asm volatile("cp.async.commit_group;")
#define CP_WAIT(N)  asm volatile("cp.async.wait_group %0;" :: "n"(N))

// ---------------------------------------------------------------------------
// fp32 -> bf16 hi/lo split
// ---------------------------------------------------------------------------
__global__ void conv_hilo(const float* __restrict__ src,
                          __nv_bfloat16* __restrict__ hi,
                          __nv_bfloat16* __restrict__ lo, int n4) {
    int i = blockIdx.x * 256 + threadIdx.x;
    if (i >= n4) return;
    float4 v = ((const float4*)src)[i];
    float f[4] = {v.x, v.y, v.z, v.w};
    uint32_t hp[4], lp[4];
    #pragma unroll
    for (int k = 0; k < 4; k++) {
        __nv_bfloat16 h = __float2bfloat16(f[k]);
        __nv_bfloat16 l = __float2bfloat16(f[k] - __bfloat162float(h));
        hp[k] = (uint32_t)__bfloat16_as_ushort(h);
        lp[k] = (uint32_t)__bfloat16_as_ushort(l);
    }
    uint2 ho, lu;
    ho.x = hp[0] | (hp[1] << 16); ho.y = hp[2] | (hp[3] << 16);
    lu.x = lp[0] | (lp[1] << 16); lu.y = lp[2] | (lp[3] << 16);
    *(uint2*)(hi + (size_t)4 * i) = ho;
    *(uint2*)(lo + (size_t)4 * i) = lu;
}

// ---------------------------------------------------------------------------
// HMMA NT-GEMM: C[M,N] (+)= A[M,K]*B[N,K]^T + bias, 3-term bf16 split.
// 128x128 CTA tile, BK=32, double-buffered cp.async, 8 warps (64x32 each).
// Smem rows padded to 80B -> conflict-free ldmatrix without swizzle.
// ---------------------------------------------------------------------------
#define RS_       80
#define TILE_B    (128 * RS_)       // 10240
#define STAGE_B   (4 * TILE_B)      // 40960: Ahi|Alo|Bhi|Blo
#define GEMM_SMEM (2 * STAGE_B)     // 81920

__global__ __launch_bounds__(256)
void hmma_gemm(const __nv_bfloat16* __restrict__ Ahi, const __nv_bfloat16* __restrict__ Alo,
               const __nv_bfloat16* __restrict__ Bhi, const __nv_bfloat16* __restrict__ Blo,
               const float* __restrict__ bias, float* __restrict__ C,
               int M, int N, int Kd, int accumulate) {
    extern __shared__ char sm[];
    uint32_t smb = smem_u32(sm);
    int tid = threadIdx.x, wid = tid >> 5, lane = tid & 31;
    size_t m0 = (size_t)blockIdx.y * 128;
    size_t n0 = (size_t)blockIdx.x * 128;
    int wm = (wid & 1) * 64;       // warp m offset
    int wn = (wid >> 1) * 32;      // warp n offset

    const __nv_bfloat16* tbase[4] = {
        Ahi + m0 * (size_t)Kd, Alo + m0 * (size_t)Kd,
        Bhi + n0 * (size_t)Kd, Blo + n0 * (size_t)Kd };

    // stage loader: 4 tiles x 128 rows x 2 chunks-per-thread
    auto load_stage = [&](int i, int s) {
        int k0 = i << 5;
        #pragma unroll
        for (int tile = 0; tile < 4; tile++) {
            #pragma unroll
            for (int t = 0; t < 2; t++) {
                int idx = tid + t * 256;        // 0..511
                int row = idx >> 2, ch = idx & 3;
                const void* src = tbase[tile] + (size_t)row * Kd + k0 + ch * 8;
                uint32_t dst = smb + s * STAGE_B + tile * TILE_B + row * RS_ + ch * 16;
                CP_ASYNC(dst, src);
            }
        }
        CP_COMMIT();
    };

    float acc[4][4][4];
    #pragma unroll
    for (int a = 0; a < 4; a++)
        #pragma unroll
        for (int b = 0; b < 4; b++)
            #pragma unroll
            for (int c = 0; c < 4; c++) acc[a][b][c] = 0.f;

    int NC = Kd >> 5;
    load_stage(0, 0);

    int r16 = lane & 15;             // A ldmatrix row
    int ah16 = (lane >> 4) * 16;     // A ldmatrix halfcol byte offset
    int rn = lane & 7;               // B ldmatrix row
    int bh16 = ((lane >> 3) & 1) * 16;

    for (int i = 0; i < NC; i++) {
        int s = i & 1;
        if (i + 1 < NC) { load_stage(i + 1, s ^ 1); CP_WAIT(1); }
        else            { CP_WAIT(0); }
        __syncthreads();

        uint32_t sa = smb + s * STAGE_B;
        #pragma unroll
        for (int j = 0; j < 2; j++) {     // two k16 steps per BK=32
            uint32_t a_hi[4][4], a_lo[4][4];
            #pragma unroll
            for (int mt = 0; mt < 4; mt++) {
                uint32_t addr = sa + (wm + mt * 16 + r16) * RS_ + ah16 + j * 32;
                ldmatrix_x4(a_hi[mt], addr);
                ldmatrix_x4(a_lo[mt], addr + TILE_B);
            }
            uint32_t b_hi[4][2], b_lo[4][2];
            #pragma unroll
            for (int nt = 0; nt < 4; nt++) {
                uint32_t addr = sa + 2 * TILE_B + (wn + nt * 8 + rn) * RS_ + bh16 + j * 32;
                ldmatrix_x2(b_hi[nt], addr);
                ldmatrix_x2(b_lo[nt], addr + TILE_B);
            }
            #pragma unroll
            for (int mt = 0; mt < 4; mt++)
                #pragma unroll
                for (int nt = 0; nt < 4; nt++)
                    mma_bf16(acc[mt][nt], a_hi[mt], b_hi[nt]);
            #pragma unroll
            for (int mt = 0; mt < 4; mt++)
                #pragma unroll
                for (int nt = 0; nt < 4; nt++)
                    mma_bf16(acc[mt][nt], a_hi[mt], b_lo[nt]);
            #pragma unroll
            for (int mt = 0; mt < 4; mt++)
                #pragma unroll
                for (int nt = 0; nt < 4; nt++)
                    mma_bf16(acc[mt][nt], a_lo[mt], b_hi[nt]);
        }
        __syncthreads();
    }

    // epilogue
    int gr = lane >> 2;
    int gc = (lane & 3) * 2;
    #pragma unroll
    for (int mt = 0; mt < 4; mt++) {
        size_t row = m0 + wm + mt * 16 + gr;
        #pragma unroll
        for (int nt = 0; nt < 4; nt++) {
            size_t col = n0 + wn + nt * 8 + gc;
            float2 bv = *(const float2*)(bias + col);
            float2 v0, v1;
            v0.x = acc[mt][nt][0] + bv.x; v0.y = acc[mt][nt][1] + bv.y;
            v1.x = acc[mt][nt][2] + bv.x; v1.y = acc[mt][nt][3] + bv.y;
            float* p0 = C + row * (size_t)N + col;
            float* p1 = C + (row + 8) * (size_t)N + col;
            if (accumulate) {
                float2 o0 = *(float2*)p0, o1 = *(float2*)p1;
                v0.x += o0.x; v0.y += o0.y; v1.x += o1.x; v1.y += o1.y;
            }
            *(float2*)p0 = v0;
            *(float2*)p1 = v1;
        }
    }
}

// ---------------------------------------------------------------------------
// Embedding
// ---------------------------------------------------------------------------
__global__ void embed_kernel(const int* __restrict__ tokens,
                             const float* __restrict__ embed,
                             const float* __restrict__ pos) {
    int row = blockIdx.x;
    int t = row & (T_ - 1);
    int tok = tokens[row];
    const float4* e = (const float4*)(embed + (size_t)tok * D_);
    const float4* p = (const float4*)(pos + (size_t)t * D_);
    float4* o = (float4*)(g_x + (size_t)row * D_);
    int c = threadIdx.x;
    float4 ev = e[c], pv = p[c];
    ev.x += pv.x; ev.y += pv.y; ev.z += pv.z; ev.w += pv.w;
    o[c] = ev;
}

// ---------------------------------------------------------------------------
// Kuramoto (attention bias cancels in softmax; phases only feed output tail)
// ---------------------------------------------------------------------------
__global__ void kuramoto_kernel(const float* __restrict__ phase,
                                const float* __restrict__ freq,
                                const float* __restrict__ coupling,
                                const float* __restrict__ nbr_w,
                                const int* __restrict__ nbr_idx,
                                float* __restrict__ out_tail) {
    int i = threadIdx.x;
    if (i < L_ * H_) {
        int l = i / H_;
        float ph = phase[i];
        float sync = 0.0f;
        #pragma unroll
        for (int k = 0; k < KNB_; k++) {
            int id = nbr_idx[i * KNB_ + k];
            sync += nbr_w[i * KNB_ + k] * sinf(phase[l * H_ + id] - ph);
        }
        out_tail[i] = ph + DT_ * (freq[i] + coupling[l] * sync);
    }
}

// ---------------------------------------------------------------------------
// LayerNorm
// ---------------------------------------------------------------------------
__global__ void ln_kernel(const float* __restrict__ x,
                          const float* __restrict__ g,
                          const float* __restrict__ b,
                          float* __restrict__ out) {
    int row = blockIdx.x;
    int c = threadIdx.x;
    float4 v = ((const float4*)(x + (size_t)row * D_))[c];
    float s  = v.x + v.y + v.z + v.w;
    float s2 = v.x * v.x + v.y * v.y + v.z * v.z + v.w * v.w;
    #pragma unroll
    for (int o = 16; o; o >>= 1) {
        s  += __shfl_down_sync(0xFFFFFFFFu, s, o);
        s2 += __shfl_down_sync(0xFFFFFFFFu, s2, o);
    }
    __shared__ float ss[8], ss2[8];
    __shared__ float mu_s, rstd_s;
    if ((c & 31) == 0) { ss[c >> 5] = s; ss2[c >> 5] = s2; }
    __syncthreads();
    if (c == 0) {
        float S = 0.f, S2 = 0.f;
        #pragma unroll
        for (int i = 0; i < 8; i++) { S += ss[i]; S2 += ss2[i]; }
        float mu = S * (1.0f / D_);
        float var = S2 * (1.0f / D_) - mu * mu;
        mu_s = mu;
        rstd_s = rsqrtf(var + 1e-5f);
    }
    __syncthreads();
    float mu = mu_s, rstd = rstd_s;
    float4 gv = ((const float4*)g)[c];
    float4 bv = ((const float4*)b)[c];
    float4 o4;
    o4.x = (v.x - mu) * rstd * gv.x + bv.x;
    o4.y = (v.y - mu) * rstd * gv.y + bv.y;
    o4.z = (v.z - mu) * rstd * gv.z + bv.z;
    o4.w = (v.w - mu) * rstd * gv.w + bv.w;
    ((float4*)(out + (size_t)row * D_))[c] = o4;
}

// ---------------------------------------------------------------------------
// Attention scores (SIMT fp32)
// ---------------------------------------------------------------------------
__global__ __launch_bounds__(256)
void scores_kernel(float scale) {
    int bh = blockIdx.z;
    int b = bh >> 4, h = bh & 15;
    const float* qb = g_qkv + (size_t)b * T_ * 3 * D_ + h * DH_;
    const float* kb = qb + D_;
    __shared__ float Qs[64][65];
    __shared__ float Ks[64][65];
    int q0 = blockIdx.y * 64, k0 = blockIdx.x * 64;
    int tid = threadIdx.x;
    #pragma unroll
    for (int it = 0; it < 4; it++) {
        int i = tid + it * 256;
        int r = i >> 4, c4 = (i & 15) * 4;
        float4 qv = *(const float4*)(qb + (size_t)(q0 + r) * 3 * D_ + c4);
        Qs[r][c4] = qv.x; Qs[r][c4 + 1] = qv.y; Qs[r][c4 + 2] = qv.z; Qs[r][c4 + 3] = qv.w;
        float4 kv = *(const float4*)(kb + (size_t)(k0 + r) * 3 * D_ + c4);
        Ks[r][c4] = kv.x; Ks[r][c4 + 1] = kv.y; Ks[r][c4 + 2] = kv.z; Ks[r][c4 + 3] = kv.w;
    }
    __syncthreads();
    int tx = tid & 15, ty = tid >> 4;
    float acc[4][4] = {};
    #pragma unroll 8
    for (int d = 0; d < DH_; d++) {
        float a[4], bb[4];
        #pragma unroll
        for (int i = 0; i < 4; i++) a[i] = Qs[ty * 4 + i][d];
        #pragma unroll
        for (int j = 0; j < 4; j++) bb[j] = Ks[tx * 4 + j][d];
        #pragma unroll
        for (int i = 0; i < 4; i++)
            #pragma unroll
            for (int j = 0; j < 4; j++)
                acc[i][j] += a[i] * bb[j];
    }
    float* srow = g_scores + (size_t)bh * T_ * T_;
    #pragma unroll
    for (int i = 0; i < 4; i++) {
        float4 r;
        r.x = acc[i][0] * scale; r.y = acc[i][1] * scale;
        r.z = acc[i][2] * scale; r.w = acc[i][3] * scale;
        *(float4*)(srow + (size_t)(q0 + ty * 4 + i) * T_ + k0 + tx * 4) = r;
    }
}

// ---------------------------------------------------------------------------
// Row softmax over T=1024
// ---------------------------------------------------------------------------
__global__ void softmax_kernel() {
    size_t row = blockIdx.x;
    int c = threadIdx.x;
    float4* rp = (float4*)(g_scores + row * T_);
    float4 v = rp[c];
    float m = fmaxf(fmaxf(v.x, v.y), fmaxf(v.z, v.w));
    #pragma unroll
    for (int o = 16; o; o >>= 1) m = fmaxf(m, __shfl_down_sync(0xFFFFFFFFu, m, o));
    __shared__ float sm[8];
    __shared__ float bm, bs;
    if ((c & 31) == 0) sm[c >> 5] = m;
    __syncthreads();
    if (c == 0) {
        float mm = sm[0];
        #pragma unroll
        for (int i = 1; i < 8; i++) mm = fmaxf(mm, sm[i]);
        bm = mm;
    }
    __syncthreads();
    float mm = bm;
    v.x = expf(v.x - mm); v.y = expf(v.y - mm);
    v.z = expf(v.z - mm); v.w = expf(v.w - mm);
    float s = v.x + v.y + v.z + v.w;
    #pragma unroll
    for (int o = 16; o; o >>= 1) s += __shfl_down_sync(0xFFFFFFFFu, s, o);
    if ((c & 31) == 0) sm[c >> 5] = s;
    __syncthreads();
    if (c == 0) {
        float S = 0.f;
        #pragma unroll
        for (int i = 0; i < 8; i++) S += sm[i];
        bs = 1.0f / S;
    }
    __syncthreads();
    float inv = bs;
    v.x *= inv; v.y *= inv; v.z *= inv; v.w *= inv;
    rp[c] = v;
}

// ---------------------------------------------------------------------------
// AV (SIMT fp32)
// ---------------------------------------------------------------------------
__global__ __launch_bounds__(256)
void av_kernel() {
    int bh = blockIdx.y;
    int b = bh >> 4, h = bh & 15;
    int q0 = blockIdx.x * 64;
    const float* vb = g_qkv + (size_t)b * T_ * 3 * D_ + 2 * D_ + h * DH_;
    const float* srow = g_scores + (size_t)bh * T_ * T_;
    __shared__ float Ss[64][65];
    __shared__ float Vs[64][65];
    int tid = threadIdx.x;
    int tx = tid & 15, ty = tid >> 4;
    float acc[4][4] = {};
    for (int kk0 = 0; kk0 < T_; kk0 += 64) {
        #pragma unroll
        for (int it = 0; it < 4; it++) {
            int i = tid + it * 256;
            int r = i >> 4, c4 = (i & 15) * 4;
            float4 sv = *(const float4*)(srow + (size_t)(q0 + r) * T_ + kk0 + c4);
            Ss[r][c4] = sv.x; Ss[r][c4 + 1] = sv.y; Ss[r][c4 + 2] = sv.z; Ss[r][c4 + 3] = sv.w;
            float4 vv = *(const float4*)(vb + (size_t)(kk0 + r) * 3 * D_ + c4);
            Vs[r][c4] = vv.x; Vs[r][c4 + 1] = vv.y; Vs[r][c4 + 2] = vv.z; Vs[r][c4 + 3] = vv.w;
        }
        __syncthreads();
        #pragma unroll 8
        for (int k = 0; k < 64; k++) {
            float a[4], bb[4];
            #pragma unroll
            for (int i = 0; i < 4; i++) a[i] = Ss[ty * 4 + i][k];
            #pragma unroll
            for (int j = 0; j < 4; j++) bb[j] = Vs[k][tx * 4 + j];
            #pragma unroll
            for (int i = 0; i < 4; i++)
                #pragma unroll
                for (int j = 0; j < 4; j++)
                    acc[i][j] += a[i] * bb[j];
        }
        __syncthreads();
    }
    #pragma unroll
    for (int i = 0; i < 4; i++) {
        float4 r;
        r.x = acc[i][0]; r.y = acc[i][1]; r.z = acc[i][2]; r.w = acc[i][3];
        *(float4*)(g_attn + (size_t)(b * T_ + q0 + ty * 4 + i) * D_ + h * DH_ + tx * 4) = r;
    }
}

// ---------------------------------------------------------------------------
// GELU (tanh approx)
// ---------------------------------------------------------------------------
__global__ void gelu_kernel(float* __restrict__ x) {
    size_t i = ((size_t)blockIdx.x * 256 + threadIdx.x) * 4;
    float4 v = *(float4*)(x + i);
    #pragma unroll
    for (int k = 0; k < 4; k++) {
        float t = ((float*)&v)[k];
        float u = 0.7978845608028654f * (t + 0.044715f * t * t * t);
        ((float*)&v)[k] = 0.5f * t * (1.0f + tanhf(u));
    }
    *(float4*)(x + i) = v;
}

// ---------------------------------------------------------------------------
// Host launcher
// ---------------------------------------------------------------------------
static inline void launch_conv(const float* src, __nv_bfloat16* hi, __nv_bfloat16* lo, size_t n) {
    int n4 = (int)(n / 4);
    conv_hilo<<<(n4 + 255) / 256, 256>>>(src, hi, lo, n4);
}

extern "C" void kernel_launch(void* const* d_in, const int* in_sizes, int n_in,
                              void* d_out, int out_size) {
    const int*   tokens   = (const int*)  d_in[0];
    const float* embed    = (const float*)d_in[1];
    const float* pos      = (const float*)d_in[2];
    const float* qkv_w    = (const float*)d_in[3];
    const float* qkv_b    = (const float*)d_in[4];
    const float* out_w    = (const float*)d_in[5];
    const float* out_b    = (const float*)d_in[6];
    const float* fc1_w    = (const float*)d_in[7];
    const float* fc1_b    = (const float*)d_in[8];
    const float* fc2_w    = (const float*)d_in[9];
    const float* fc2_b    = (const float*)d_in[10];
    const float* ln1_g    = (const float*)d_in[11];
    const float* ln1_b    = (const float*)d_in[12];
    const float* ln2_g    = (const float*)d_in[13];
    const float* ln2_b    = (const float*)d_in[14];
    const float* lnf_g    = (const float*)d_in[15];
    const float* lnf_b    = (const float*)d_in[16];
    const float* head_w   = (const float*)d_in[17];
    const float* head_b   = (const float*)d_in[18];
    const float* phase    = (const float*)d_in[19];
    const float* freq     = (const float*)d_in[20];
    const float* coupling = (const float*)d_in[21];
    const float* nbr_w    = (const float*)d_in[22];
    const int*   nbr_idx  = (const int*)  d_in[23];
    float* out = (float*)d_out;

    float *px, *ph, *pqkv, *pattn, *pff;
    __nv_bfloat16 *pwh, *pwl, *pah, *pal;
    cudaGetSymbolAddress((void**)&px, g_x);
    cudaGetSymbolAddress((void**)&ph, g_h);
    cudaGetSymbolAddress((void**)&pqkv, g_qkv);
    cudaGetSymbolAddress((void**)&pattn, g_attn);
    cudaGetSymbolAddress((void**)&pff, g_ff);
    cudaGetSymbolAddress((void**)&pwh, g_w_hi);
    cudaGetSymbolAddress((void**)&pwl, g_w_lo);
    cudaGetSymbolAddress((void**)&pah, g_act_hi);
    cudaGetSymbolAddress((void**)&pal, g_act_lo);

    cudaFuncSetAttribute(hmma_gemm, cudaFuncAttributeMaxDynamicSharedMemorySize, GEMM_SMEM);

    const int M = B_ * T_;
    const float scale = 1.0f / 8.0f;

    kuramoto_kernel<<<1, 128>>>(phase, freq, coupling, nbr_w, nbr_idx,
                                out + (size_t)B_ * T_ * V_);
    embed_kernel<<<M, 256>>>(tokens, embed, pos);

    // one-time weight conversions
    launch_conv(qkv_w,  pwh + W_QKV_OFF,  pwl + W_QKV_OFF,  W_QKV_N);
    launch_conv(out_w,  pwh + W_OUT_OFF,  pwl + W_OUT_OFF,  W_OUT_N);
    launch_conv(fc1_w,  pwh + W_FC1_OFF,  pwl + W_FC1_OFF,  W_FC1_N);
    launch_conv(fc2_w,  pwh + W_FC2_OFF,  pwl + W_FC2_OFF,  W_FC2_N);
    launch_conv(head_w, pwh + W_HEAD_OFF, pwl + W_HEAD_OFF, W_HEAD_N);

    for (int l = 0; l < L_; l++) {
        ln_kernel<<<M, 256>>>(px, ln1_g + l * D_, ln1_b + l * D_, ph);
        launch_conv(ph, pah, pal, (size_t)M * D_);
        hmma_gemm<<<dim3(3 * D_ / 128, M / 128), 256, GEMM_SMEM>>>(
            pah, pal,
            pwh + W_QKV_OFF + (size_t)l * 3 * D_ * D_, pwl + W_QKV_OFF + (size_t)l * 3 * D_ * D_,
            qkv_b + l * 3 * D_, pqkv, M, 3 * D_, D_, 0);
        scores_kernel<<<dim3(T_ / 64, T_ / 64, B_ * H_), 256>>>(scale);
        softmax_kernel<<<B_ * H_ * T_, 256>>>();
        av_kernel<<<dim3(T_ / 64, B_ * H_), 256>>>();
        launch_conv(pattn, pah, pal, (size_t)M * D_);
        hmma_gemm<<<dim3(D_ / 128, M / 128), 256, GEMM_SMEM>>>(
            pah, pal,
            pwh + W_OUT_OFF + (size_t)l * D_ * D_, pwl + W_OUT_OFF + (size_t)l * D_ * D_,
            out_b + l * D_, px, M, D_, D_, 1);
        ln_kernel<<<M, 256>>>(px, ln2_g + l * D_, ln2_b + l * D_, ph);
        launch_conv(ph, pah, pal, (size_t)M * D_);
        hmma_gemm<<<dim3(FF_ / 128, M / 128), 256, GEMM_SMEM>>>(
            pah, pal,
            pwh + W_FC1_OFF + (size_t)l * FF_ * D_, pwl + W_FC1_OFF + (size_t)l * FF_ * D_,
            fc1_b + l * FF_, pff, M, FF_, D_, 0);
        gelu_kernel<<<(M * FF_) / 1024, 256>>>(pff);
        launch_conv(pff, pah, pal, (size_t)M * FF_);
        hmma_gemm<<<dim3(D_ / 128, M / 128), 256, GEMM_SMEM>>>(
            pah, pal,
            pwh + W_FC2_OFF + (size_t)l * D_ * FF_, pwl + W_FC2_OFF + (size_t)l * D_ * FF_,
            fc2_b + l * D_, px, M, D_, FF_, 1);
    }

    ln_kernel<<<M, 256>>>(px, lnf_g, lnf_b, ph);
    launch_conv(ph, pah, pal, (size_t)M * D_);
    hmma_gemm<<<dim3(V_ / 128, M / 128), 256, GEMM_SMEM>>>(
        pah, pal, pwh + W_HEAD_OFF, pwl + W_HEAD_OFF,
        head_b, out, M, V_, D_, 0);
}